// round 6
// baseline (speedup 1.0000x reference)
#include <cuda_runtime.h>

#define BATCH 1024
#define PIX   784

// Scratch (allocation-free rule: __device__ globals)
__device__ float g_feat[BATCH * 64];    // [B][branch0 32 | branch1 32]
__device__ float g_hconv[BATCH * PIX];  // CNN branch output, flattened

// ---------------------------------------------------------------------------
// Kernel 1: persistence-landscape features.
// Insight: tent(v) = max(0, min(t - v, death - t)) is non-increasing in v,
// so top-2 over p at every t = tents of the two SMALLEST v. Only need
// (min1, min2, max) per sample, then 64 closed-form values + tiny GEMM.
// ---------------------------------------------------------------------------
__global__ void __launch_bounds__(256) feat_kernel(
    const float* __restrict__ v005, const float* __restrict__ v02,
    const float* __restrict__ g1w, const float* __restrict__ g1b,
    const float* __restrict__ g2w, const float* __restrict__ g2b)
{
    __shared__ float red1[8], red2[8], redm[8];
    __shared__ float stats[2][3];   // min1, min2, max per branch
    __shared__ float xls[2][64];    // landscape vectors (k*32 + t layout)

    const int tid  = threadIdx.x;
    const int lane = tid & 31, wid = tid >> 5;
    const int b    = blockIdx.x;

    for (int br = 0; br < 2; br++) {
        const float* v = (br ? v02 : v005) + b * PIX;
        float m1 = 1e30f, m2 = 1e30f, mx = -1e30f;
        for (int i = tid; i < PIX; i += 256) {
            const float xv = v[i];
            mx = fmaxf(mx, xv);
            const float hi = fmaxf(m1, xv);
            m1 = fminf(m1, xv);
            m2 = fminf(m2, hi);
        }
        #pragma unroll
        for (int o = 16; o; o >>= 1) {
            const float o1 = __shfl_xor_sync(0xFFFFFFFFu, m1, o);
            const float o2 = __shfl_xor_sync(0xFFFFFFFFu, m2, o);
            const float om = __shfl_xor_sync(0xFFFFFFFFu, mx, o);
            const float hi = fmaxf(m1, o1);
            m1 = fminf(m1, o1);
            m2 = fminf(hi, fminf(m2, o2));
            mx = fmaxf(mx, om);
        }
        if (lane == 0) { red1[wid] = m1; red2[wid] = m2; redm[wid] = mx; }
        __syncthreads();
        if (tid == 0) {
            float a1 = red1[0], a2 = red2[0], am = redm[0];
            #pragma unroll
            for (int w = 1; w < 8; w++) {
                const float o1 = red1[w], o2 = red2[w];
                const float hi = fmaxf(a1, o1);
                a1 = fminf(a1, o1);
                a2 = fminf(hi, fminf(a2, o2));
                am = fmaxf(am, redm[w]);
            }
            stats[br][0] = a1; stats[br][1] = a2; stats[br][2] = am;
        }
        __syncthreads();   // also guards red* reuse by next branch
    }

    // 64 landscape values per branch: xls[br][k*32 + t]
    if (tid < 128) {
        const int br = tid >> 6, i = tid & 63;
        const int k = i >> 5, t = i & 31;
        const float t0 = br ? 0.05f : 0.01f;
        const float dt = br ? (0.25f / 31.0f) : (0.28f / 31.0f);
        const float tv = t0 + (float)t * dt;
        xls[br][i] = fmaxf(0.f, fminf(tv - stats[br][k], stats[br][2] - tv));
    }
    __syncthreads();

    // relu(xls @ g_w + g_b): 32 outputs per branch
    if (tid < 64) {
        const int br = tid >> 5, f = tid & 31;
        const float* gw = br ? g2w : g1w;
        float a = (br ? g2b : g1b)[f];
        #pragma unroll
        for (int i = 0; i < 64; i++) a += xls[br][i] * gw[i * 32 + f];
        g_feat[b * 64 + br * 32 + f] = fmaxf(a, 0.f);
    }
}

// ---------------------------------------------------------------------------
// Kernel 2: fused conv(1->32,3x3,SAME) -> relu -> conv(32->1,3x3,SAME) -> relu.
// One block per sample. 196 active threads: (28 cols) x (7 groups of 4 rows).
// conv1 inputs fully register-hoisted (reused for all 32 channels);
// mid channels staged in shared in groups of 8 (halo-zeroed once).
// ---------------------------------------------------------------------------
__global__ void __launch_bounds__(224) conv_kernel(
    const float* __restrict__ x,
    const float* __restrict__ w1, const float* __restrict__ b1,
    const float* __restrict__ w2, const float* __restrict__ b2)
{
    __shared__ float xs[30][32];        // input with zero halo
    __shared__ float mids[8][30][32];   // per-channel-group mid, zero halo
    __shared__ float w1s[288];
    __shared__ float w2s[288];
    __shared__ float b1s[32];
    __shared__ float b2s;

    const int tid = threadIdx.x;
    const int b   = blockIdx.x;

    for (int i = tid; i < 30 * 32; i += 224)     (&xs[0][0])[i] = 0.f;
    for (int i = tid; i < 8 * 30 * 32; i += 224) (&mids[0][0][0])[i] = 0.f;
    for (int i = tid; i < 288; i += 224) { w1s[i] = w1[i]; w2s[i] = w2[i]; }
    if (tid < 32) b1s[tid] = b1[tid];
    if (tid == 0) b2s = b2[0];
    __syncthreads();

    const float* xb = x + b * PIX;
    for (int i = tid; i < PIX; i += 224)
        xs[i / 28 + 1][i % 28 + 1] = xb[i];
    __syncthreads();

    const bool active = tid < 196;
    const int xcol = tid % 28;
    const int y0   = (tid / 28) * 4;

    float xr[6][3];   // input window for 4-row tile, reused across 32 channels
    if (active) {
        #pragma unroll
        for (int rr = 0; rr < 6; rr++)
            #pragma unroll
            for (int dx = 0; dx < 3; dx++)
                xr[rr][dx] = xs[y0 + rr][xcol + dx];
    }
    const float bb = b2s;
    float a0 = bb, a1 = bb, a2 = bb, a3 = bb;

    for (int g = 0; g < 4; g++) {
        if (active) {
            #pragma unroll
            for (int cc = 0; cc < 8; cc++) {
                const int c = g * 8 + cc;
                float m0 = b1s[c], m1 = m0, m2 = m0, m3 = m0;
                #pragma unroll
                for (int dy = 0; dy < 3; dy++)
                    #pragma unroll
                    for (int dx = 0; dx < 3; dx++) {
                        const float w = w1s[(dy * 3 + dx) * 32 + c];
                        m0 += xr[0 + dy][dx] * w;
                        m1 += xr[1 + dy][dx] * w;
                        m2 += xr[2 + dy][dx] * w;
                        m3 += xr[3 + dy][dx] * w;
                    }
                mids[cc][y0 + 1][xcol + 1] = fmaxf(m0, 0.f);
                mids[cc][y0 + 2][xcol + 1] = fmaxf(m1, 0.f);
                mids[cc][y0 + 3][xcol + 1] = fmaxf(m2, 0.f);
                mids[cc][y0 + 4][xcol + 1] = fmaxf(m3, 0.f);
            }
        }
        __syncthreads();
        if (active) {
            #pragma unroll
            for (int cc = 0; cc < 8; cc++) {
                const int c = g * 8 + cc;
                float mr[6][3];
                #pragma unroll
                for (int rr = 0; rr < 6; rr++)
                    #pragma unroll
                    for (int dx = 0; dx < 3; dx++)
                        mr[rr][dx] = mids[cc][y0 + rr][xcol + dx];
                #pragma unroll
                for (int dy = 0; dy < 3; dy++)
                    #pragma unroll
                    for (int dx = 0; dx < 3; dx++) {
                        const float w = w2s[(dy * 3 + dx) * 32 + c];
                        a0 += mr[0 + dy][dx] * w;
                        a1 += mr[1 + dy][dx] * w;
                        a2 += mr[2 + dy][dx] * w;
                        a3 += mr[3 + dy][dx] * w;
                    }
            }
        }
        __syncthreads();
    }
    if (active) {
        float* hout = g_hconv + b * PIX + y0 * 28 + xcol;
        hout[0]  = fmaxf(a0, 0.f);
        hout[28] = fmaxf(a1, 0.f);
        hout[56] = fmaxf(a2, 0.f);
        hout[84] = fmaxf(a3, 0.f);
    }
}

// ---------------------------------------------------------------------------
// Kernel 3: z = [hconv(784) | feat(64)]; relu(z @ fc1_w + b) @ fc2_w + b.
// 128 blocks x 256 threads; 8 samples/block; in-block split-K over 4
// warp-quarters; MS=2 x NF=4 register tiling; fc1_w staged in dynamic smem.
// ---------------------------------------------------------------------------
#define FC_ZS    (8 * 852)        // padded z rows (852 breaks bank aliasing)
#define FC_WS    (4 * 53 * 64)    // 4 quarter chunks of staged fc1_w
#define FC_PH    (4 * 8 * 65)     // split-K partials
#define FC_HS    (8 * 65)
#define FC_SMEM_BYTES ((FC_ZS + FC_WS + FC_PH + FC_HS) * 4)

__global__ void __launch_bounds__(256) fc_kernel(
    const float* __restrict__ fc1w, const float* __restrict__ fc1b,
    const float* __restrict__ fc2w, const float* __restrict__ fc2b,
    float* __restrict__ out)
{
    extern __shared__ float sm[];
    float* zs = sm;                 // [8][852]
    float* ws = sm + FC_ZS;         // [4][53*64]
    float* ph = ws + FC_WS;         // [(q*8+s)][65]
    float* hs = ph + FC_PH;         // [8][65]

    const int tid = threadIdx.x;
    const int b0  = blockIdx.x * 8;

    for (int i = tid; i < 8 * 848; i += 256) {
        const int s = i / 848, k = i - s * 848;
        zs[s * 852 + k] = (k < 784) ? g_hconv[(b0 + s) * 784 + k]
                                    : g_feat[(b0 + s) * 64 + (k - 784)];
    }

    const int q  = tid >> 6;          // k-quarter (0..3), 212 k's each
    const int sq = (tid >> 4) & 3;    // samples sq, sq+4
    const int fq = tid & 15;          // f = fq, fq+16, fq+32, fq+48
    const int lt = tid & 63;

    float acc[2][4] = {};
    const float* z0p = zs + sq * 852;
    const float* z1p = zs + (sq + 4) * 852;
    float* wq = ws + q * (53 * 64);

    for (int c = 0; c < 4; c++) {
        __syncthreads();              // zs ready (c=0); wq consumed (c>0)
        const float* wsrc = fc1w + (q * 212 + c * 53) * 64;
        for (int i = lt; i < 53 * 64; i += 64) wq[i] = wsrc[i];
        __syncthreads();
        const int kb = q * 212 + c * 53;
        for (int kk = 0; kk < 53; kk++) {
            const float z0 = z0p[kb + kk];
            const float z1 = z1p[kb + kk];
            const float* wrow = wq + kk * 64 + fq;
            #pragma unroll
            for (int m = 0; m < 4; m++) {
                const float w = wrow[m * 16];
                acc[0][m] += z0 * w;
                acc[1][m] += z1 * w;
            }
        }
    }
    #pragma unroll
    for (int m = 0; m < 4; m++) {
        ph[(q * 8 + sq    ) * 65 + fq + m * 16] = acc[0][m];
        ph[(q * 8 + sq + 4) * 65 + fq + m * 16] = acc[1][m];
    }
    __syncthreads();
    for (int i = tid; i < 512; i += 256) {
        const int s = i >> 6, f = i & 63;
        float h = ph[s * 65 + f] + ph[(8 + s) * 65 + f]
                + ph[(16 + s) * 65 + f] + ph[(24 + s) * 65 + f] + fc1b[f];
        hs[s * 65 + f] = fmaxf(h, 0.f);
    }
    __syncthreads();
    if (tid < 80) {
        const int s = tid / 10, o = tid - s * 10;
        float a = fc2b[o];
        #pragma unroll
        for (int f = 0; f < 64; f++) a += hs[s * 65 + f] * fc2w[f * 10 + o];
        out[(b0 + s) * 10 + o] = a;
    }
}

// ---------------------------------------------------------------------------
extern "C" void kernel_launch(void* const* d_in, const int* in_sizes, int n_in,
                              void* d_out, int out_size)
{
    const float* x       = (const float*)d_in[0];
    const float* xd005   = (const float*)d_in[1];
    const float* xd02    = (const float*)d_in[2];
    const float* conv_w1 = (const float*)d_in[3];
    const float* conv_b1 = (const float*)d_in[4];
    const float* conv_w2 = (const float*)d_in[5];
    const float* conv_b2 = (const float*)d_in[6];
    const float* g1w     = (const float*)d_in[7];
    const float* g1b     = (const float*)d_in[8];
    const float* g2w     = (const float*)d_in[9];
    const float* g2b     = (const float*)d_in[10];
    const float* fc1w    = (const float*)d_in[11];
    const float* fc1b    = (const float*)d_in[12];
    const float* fc2w    = (const float*)d_in[13];
    const float* fc2b    = (const float*)d_in[14];
    float* out = (float*)d_out;

    cudaFuncSetAttribute(fc_kernel, cudaFuncAttributeMaxDynamicSharedMemorySize,
                         FC_SMEM_BYTES);

    feat_kernel<<<BATCH, 256>>>(xd005, xd02, g1w, g1b, g2w, g2b);
    conv_kernel<<<BATCH, 224>>>(x, conv_w1, conv_b1, conv_w2, conv_b2);
    fc_kernel<<<128, 256, FC_SMEM_BYTES>>>(fc1w, fc1b, fc2w, fc2b, out);
}

// round 7
// speedup vs baseline: 1.1743x; 1.1743x over previous
#include <cuda_runtime.h>

#define BATCH 1024
#define PIX   784

// Scratch (allocation-free rule: __device__ globals)
__device__ float g_feat[BATCH * 64];    // [B][branch0 32 | branch1 32]
__device__ float g_hconv[BATCH * PIX];  // CNN branch output, flattened

// ---- packed f32x2 helpers (Blackwell FFMA2: only reachable via PTX) --------
typedef unsigned long long u64;
__device__ __forceinline__ u64 pk2(float lo, float hi) {
    u64 r; asm("mov.b64 %0, {%1,%2};" : "=l"(r) : "f"(lo), "f"(hi)); return r;
}
__device__ __forceinline__ void upk2(u64 v, float& lo, float& hi) {
    asm("mov.b64 {%0,%1}, %2;" : "=f"(lo), "=f"(hi) : "l"(v));
}
__device__ __forceinline__ u64 fma2(u64 a, u64 b, u64 c) {
    u64 d; asm("fma.rn.f32x2 %0, %1, %2, %3;" : "=l"(d) : "l"(a), "l"(b), "l"(c));
    return d;
}

// ---------------------------------------------------------------------------
// Kernel 1: persistence-landscape features. One WARP per sample (no block
// reduction syncs), float4 loads, g-weights staged in smem once per block.
// tent(v) = max(0, min(t - v, death - t)) is non-increasing in v, so top-2
// over p at every t = tents of the two SMALLEST v -> only (min1,min2,max).
// ---------------------------------------------------------------------------
__global__ void __launch_bounds__(256) feat_kernel(
    const float* __restrict__ v005, const float* __restrict__ v02,
    const float* __restrict__ g1w, const float* __restrict__ g1b,
    const float* __restrict__ g2w, const float* __restrict__ g2b)
{
    __shared__ float gws[2][64 * 32];
    __shared__ float gbs[2][32];
    __shared__ float xls[8][2][64];

    const int tid  = threadIdx.x;
    const int lane = tid & 31, w = tid >> 5;
    const int b    = blockIdx.x * 8 + w;

    for (int i = tid; i < 2048; i += 256) {
        gws[0][i] = g1w[i];
        gws[1][i] = g2w[i];
    }
    if (tid < 32) { gbs[0][tid] = g1b[tid]; gbs[1][tid] = g2b[tid]; }
    __syncthreads();

    float st[2][3];
    #pragma unroll
    for (int br = 0; br < 2; br++) {
        const float4* v = (const float4*)((br ? v02 : v005) + b * PIX);
        float m1 = 1e30f, m2 = 1e30f, mx = -1e30f;
        for (int i = lane; i < 196; i += 32) {
            const float4 q = v[i];
            float hv;
            mx = fmaxf(mx, fmaxf(fmaxf(q.x, q.y), fmaxf(q.z, q.w)));
            hv = fmaxf(m1, q.x); m1 = fminf(m1, q.x); m2 = fminf(m2, hv);
            hv = fmaxf(m1, q.y); m1 = fminf(m1, q.y); m2 = fminf(m2, hv);
            hv = fmaxf(m1, q.z); m1 = fminf(m1, q.z); m2 = fminf(m2, hv);
            hv = fmaxf(m1, q.w); m1 = fminf(m1, q.w); m2 = fminf(m2, hv);
        }
        #pragma unroll
        for (int o = 16; o; o >>= 1) {
            const float o1 = __shfl_xor_sync(0xFFFFFFFFu, m1, o);
            const float o2 = __shfl_xor_sync(0xFFFFFFFFu, m2, o);
            const float om = __shfl_xor_sync(0xFFFFFFFFu, mx, o);
            const float hi = fmaxf(m1, o1);
            m1 = fminf(m1, o1);
            m2 = fminf(hi, fminf(m2, o2));
            mx = fmaxf(mx, om);
        }
        st[br][0] = m1; st[br][1] = m2; st[br][2] = mx;
    }

    // 64 landscape values per branch: xls[k*32 + t]
    #pragma unroll
    for (int br = 0; br < 2; br++) {
        const float t0 = br ? 0.05f : 0.01f;
        const float dt = br ? (0.25f / 31.0f) : (0.28f / 31.0f);
        #pragma unroll
        for (int i = lane; i < 64; i += 32) {
            const int k = i >> 5, t = i & 31;
            const float tv = t0 + (float)t * dt;
            xls[w][br][i] = fmaxf(0.f, fminf(tv - st[br][k], st[br][2] - tv));
        }
    }
    __syncwarp();

    // relu(xls @ g_w + g_b): lane = output feature
    #pragma unroll
    for (int br = 0; br < 2; br++) {
        float a = gbs[br][lane];
        #pragma unroll 8
        for (int i = 0; i < 64; i++) a += xls[w][br][i] * gws[br][i * 32 + lane];
        g_feat[b * 64 + br * 32 + lane] = fmaxf(a, 0.f);
    }
}

// ---------------------------------------------------------------------------
// Kernel 2: fused conv(1->32,3x3,SAME) -> relu -> conv(32->1,3x3,SAME) -> relu
// with CHANNEL-PAIR f32x2 packing: weight pairs (w[c],w[c+1]) are adjacent in
// memory -> free LDS.64 broadcast; mid activations stored as float2[c/2] ->
// free aligned LDS.64. FFMA2 halves the fma-pipe time vs scalar FFMA.
// One block per sample. 196 active threads: 28 cols x 7 groups of 4 rows.
// ---------------------------------------------------------------------------
__global__ void __launch_bounds__(224) conv_kernel(
    const float* __restrict__ x,
    const float* __restrict__ w1, const float* __restrict__ b1,
    const float* __restrict__ w2, const float* __restrict__ b2)
{
    __shared__ __align__(16) float  xs[30][32];       // input with zero halo
    __shared__ __align__(16) float2 mids2[4][30][32]; // cpair group, zero halo
    __shared__ __align__(16) float  w1s[288];         // [tap][32 ch]
    __shared__ __align__(16) float  w2s[288];
    __shared__ __align__(16) float  b1s[32];
    __shared__ float b2s;

    const int tid = threadIdx.x;
    const int b   = blockIdx.x;

    for (int i = tid; i < 30 * 32; i += 224) (&xs[0][0])[i] = 0.f;
    for (int i = tid; i < 4 * 30 * 32; i += 224)
        (&mids2[0][0][0])[i] = make_float2(0.f, 0.f);
    for (int i = tid; i < 288; i += 224) { w1s[i] = w1[i]; w2s[i] = w2[i]; }
    if (tid < 32) b1s[tid] = b1[tid];
    if (tid == 0) b2s = b2[0];
    __syncthreads();

    // input load: 28 % 4 == 0 so float4 never crosses a row
    if (tid < 196) {
        const float4 q = ((const float4*)(x + b * PIX))[tid];
        const int r = tid / 7, c = (tid % 7) * 4;
        xs[r + 1][c + 1] = q.x; xs[r + 1][c + 2] = q.y;
        xs[r + 1][c + 3] = q.z; xs[r + 1][c + 4] = q.w;
    }
    __syncthreads();

    const bool active = tid < 196;
    const int xcol = tid % 28;
    const int y0   = (tid / 28) * 4;

    u64 xp[6][3];   // (x,x) packs, reused across all 16 channel pairs
    if (active) {
        #pragma unroll
        for (int rr = 0; rr < 6; rr++)
            #pragma unroll
            for (int dx = 0; dx < 3; dx++) {
                const float xv = xs[y0 + rr][xcol + dx];
                xp[rr][dx] = pk2(xv, xv);
            }
    }
    u64 a0 = 0, a1 = 0, a2 = 0, a3 = 0;   // packed-over-channel accumulators

    for (int g = 0; g < 4; g++) {
        if (active) {
            #pragma unroll
            for (int cp = 0; cp < 4; cp++) {
                const int c2 = (g * 4 + cp) * 2;      // even channel index
                const u64 bv = *(const u64*)&b1s[c2];
                u64 m0 = bv, m1 = bv, m2 = bv, m3 = bv;
                #pragma unroll
                for (int dy = 0; dy < 3; dy++)
                    #pragma unroll
                    for (int dx = 0; dx < 3; dx++) {
                        const u64 wv = *(const u64*)&w1s[(dy * 3 + dx) * 32 + c2];
                        m0 = fma2(xp[0 + dy][dx], wv, m0);
                        m1 = fma2(xp[1 + dy][dx], wv, m1);
                        m2 = fma2(xp[2 + dy][dx], wv, m2);
                        m3 = fma2(xp[3 + dy][dx], wv, m3);
                    }
                float lo, hi;
                upk2(m0, lo, hi);
                mids2[cp][y0 + 1][xcol + 1] = make_float2(fmaxf(lo, 0.f), fmaxf(hi, 0.f));
                upk2(m1, lo, hi);
                mids2[cp][y0 + 2][xcol + 1] = make_float2(fmaxf(lo, 0.f), fmaxf(hi, 0.f));
                upk2(m2, lo, hi);
                mids2[cp][y0 + 3][xcol + 1] = make_float2(fmaxf(lo, 0.f), fmaxf(hi, 0.f));
                upk2(m3, lo, hi);
                mids2[cp][y0 + 4][xcol + 1] = make_float2(fmaxf(lo, 0.f), fmaxf(hi, 0.f));
            }
        }
        __syncthreads();
        if (active) {
            #pragma unroll
            for (int cp = 0; cp < 4; cp++) {
                const int c2 = (g * 4 + cp) * 2;
                #pragma unroll
                for (int dx = 0; dx < 3; dx++) {
                    u64 c[6];
                    #pragma unroll
                    for (int rr = 0; rr < 6; rr++)
                        c[rr] = *(const u64*)&mids2[cp][y0 + rr][xcol + dx];
                    #pragma unroll
                    for (int dy = 0; dy < 3; dy++) {
                        const u64 wv = *(const u64*)&w2s[(dy * 3 + dx) * 32 + c2];
                        a0 = fma2(c[0 + dy], wv, a0);
                        a1 = fma2(c[1 + dy], wv, a1);
                        a2 = fma2(c[2 + dy], wv, a2);
                        a3 = fma2(c[3 + dy], wv, a3);
                    }
                }
            }
        }
        __syncthreads();
    }
    if (active) {
        const float bb = b2s;
        float lo, hi;
        float* hout = g_hconv + b * PIX + y0 * 28 + xcol;
        upk2(a0, lo, hi); hout[0]  = fmaxf(lo + hi + bb, 0.f);
        upk2(a1, lo, hi); hout[28] = fmaxf(lo + hi + bb, 0.f);
        upk2(a2, lo, hi); hout[56] = fmaxf(lo + hi + bb, 0.f);
        upk2(a3, lo, hi); hout[84] = fmaxf(lo + hi + bb, 0.f);
    }
}

// ---------------------------------------------------------------------------
// Kernel 3: z = [hconv(784) | feat(64)]; relu(z @ fc1_w + b) @ fc2_w + b.
// 128 blocks x 256 threads; 8 samples/block; in-block split-K over 4
// warp-quarters; MS=2 x NF=4 register tiling; fc1_w staged in dynamic smem.
// ---------------------------------------------------------------------------
#define FC_ZS    (8 * 852)        // padded z rows (852 breaks bank aliasing)
#define FC_WS    (4 * 53 * 64)    // 4 quarter chunks of staged fc1_w
#define FC_PH    (4 * 8 * 65)     // split-K partials
#define FC_HS    (8 * 65)
#define FC_SMEM_BYTES ((FC_ZS + FC_WS + FC_PH + FC_HS) * 4)

__global__ void __launch_bounds__(256) fc_kernel(
    const float* __restrict__ fc1w, const float* __restrict__ fc1b,
    const float* __restrict__ fc2w, const float* __restrict__ fc2b,
    float* __restrict__ out)
{
    extern __shared__ float sm[];
    float* zs = sm;                 // [8][852]
    float* ws = sm + FC_ZS;         // [4][53*64]
    float* ph = ws + FC_WS;         // [(q*8+s)][65]
    float* hs = ph + FC_PH;         // [8][65]

    const int tid = threadIdx.x;
    const int b0  = blockIdx.x * 8;

    for (int i = tid; i < 8 * 848; i += 256) {
        const int s = i / 848, k = i - s * 848;
        zs[s * 852 + k] = (k < 784) ? g_hconv[(b0 + s) * 784 + k]
                                    : g_feat[(b0 + s) * 64 + (k - 784)];
    }

    const int q  = tid >> 6;          // k-quarter (0..3), 212 k's each
    const int sq = (tid >> 4) & 3;    // samples sq, sq+4
    const int fq = tid & 15;          // f = fq, fq+16, fq+32, fq+48
    const int lt = tid & 63;

    float acc[2][4] = {};
    const float* z0p = zs + sq * 852;
    const float* z1p = zs + (sq + 4) * 852;
    float* wq = ws + q * (53 * 64);

    for (int c = 0; c < 4; c++) {
        __syncthreads();              // zs ready (c=0); wq consumed (c>0)
        const float* wsrc = fc1w + (q * 212 + c * 53) * 64;
        for (int i = lt; i < 53 * 64; i += 64) wq[i] = wsrc[i];
        __syncthreads();
        const int kb = q * 212 + c * 53;
        for (int kk = 0; kk < 53; kk++) {
            const float z0 = z0p[kb + kk];
            const float z1 = z1p[kb + kk];
            const float* wrow = wq + kk * 64 + fq;
            #pragma unroll
            for (int m = 0; m < 4; m++) {
                const float w = wrow[m * 16];
                acc[0][m] += z0 * w;
                acc[1][m] += z1 * w;
            }
        }
    }
    #pragma unroll
    for (int m = 0; m < 4; m++) {
        ph[(q * 8 + sq    ) * 65 + fq + m * 16] = acc[0][m];
        ph[(q * 8 + sq + 4) * 65 + fq + m * 16] = acc[1][m];
    }
    __syncthreads();
    for (int i = tid; i < 512; i += 256) {
        const int s = i >> 6, f = i & 63;
        float h = ph[s * 65 + f] + ph[(8 + s) * 65 + f]
                + ph[(16 + s) * 65 + f] + ph[(24 + s) * 65 + f] + fc1b[f];
        hs[s * 65 + f] = fmaxf(h, 0.f);
    }
    __syncthreads();
    if (tid < 80) {
        const int s = tid / 10, o = tid - s * 10;
        float a = fc2b[o];
        #pragma unroll
        for (int f = 0; f < 64; f++) a += hs[s * 65 + f] * fc2w[f * 10 + o];
        out[(b0 + s) * 10 + o] = a;
    }
}

// ---------------------------------------------------------------------------
extern "C" void kernel_launch(void* const* d_in, const int* in_sizes, int n_in,
                              void* d_out, int out_size)
{
    const float* x       = (const float*)d_in[0];
    const float* xd005   = (const float*)d_in[1];
    const float* xd02    = (const float*)d_in[2];
    const float* conv_w1 = (const float*)d_in[3];
    const float* conv_b1 = (const float*)d_in[4];
    const float* conv_w2 = (const float*)d_in[5];
    const float* conv_b2 = (const float*)d_in[6];
    const float* g1w     = (const float*)d_in[7];
    const float* g1b     = (const float*)d_in[8];
    const float* g2w     = (const float*)d_in[9];
    const float* g2b     = (const float*)d_in[10];
    const float* fc1w    = (const float*)d_in[11];
    const float* fc1b    = (const float*)d_in[12];
    const float* fc2w    = (const float*)d_in[13];
    const float* fc2b    = (const float*)d_in[14];
    float* out = (float*)d_out;

    cudaFuncSetAttribute(fc_kernel, cudaFuncAttributeMaxDynamicSharedMemorySize,
                         FC_SMEM_BYTES);

    feat_kernel<<<128, 256>>>(xd005, xd02, g1w, g1b, g2w, g2b);
    conv_kernel<<<BATCH, 224>>>(x, conv_w1, conv_b1, conv_w2, conv_b2);
    fc_kernel<<<128, 256, FC_SMEM_BYTES>>>(fc1w, fc1b, fc2w, fc2b, out);
}

// round 8
// speedup vs baseline: 1.2633x; 1.0758x over previous
#include <cuda_runtime.h>

#define BATCH 1024
#define PIX   784

// Scratch (allocation-free rule: __device__ globals)
__device__ float g_feat[BATCH * 64];    // [B][branch0 32 | branch1 32]
__device__ float g_hconv[BATCH * PIX];  // CNN branch output, flattened

// ---- packed f32x2 helpers (Blackwell FFMA2: only reachable via PTX) --------
typedef unsigned long long u64;
__device__ __forceinline__ u64 pk2(float lo, float hi) {
    u64 r; asm("mov.b64 %0, {%1,%2};" : "=l"(r) : "f"(lo), "f"(hi)); return r;
}
__device__ __forceinline__ void upk2(u64 v, float& lo, float& hi) {
    asm("mov.b64 {%0,%1}, %2;" : "=f"(lo), "=f"(hi) : "l"(v));
}
__device__ __forceinline__ u64 fma2(u64 a, u64 b, u64 c) {
    u64 d; asm("fma.rn.f32x2 %0, %1, %2, %3;" : "=l"(d) : "l"(a), "l"(b), "l"(c));
    return d;
}

// ---------------------------------------------------------------------------
// Kernel 1 (fused): per-sample block does BOTH:
//  (a) persistence-landscape features. tent(v)=max(0,min(t-v,death-t)) is
//      non-increasing in v, so top-2 over p at every t = tents of the two
//      SMALLEST v -> only (min1,min2,max) per sample + 64 closed-form evals
//      + 64x64 matvec. DRAM latency hides behind conv FMA work.
//  (b) fused conv(1->32,3x3,SAME)->relu->conv(32->1,3x3,SAME)->relu with
//      CHANNEL-PAIR f32x2 packing (weight pairs adjacent -> free LDS.64;
//      mids stored as float2 -> free LDS.64). FFMA2 = 2x fma throughput.
// 224 threads; 196 active for conv: 28 cols x 7 groups of 4 rows.
// ---------------------------------------------------------------------------
__global__ void __launch_bounds__(224) conv_feat_kernel(
    const float* __restrict__ x,
    const float* __restrict__ w1, const float* __restrict__ b1,
    const float* __restrict__ w2, const float* __restrict__ b2,
    const float* __restrict__ v005, const float* __restrict__ v02,
    const float* __restrict__ g1w, const float* __restrict__ g1b,
    const float* __restrict__ g2w, const float* __restrict__ g2b)
{
    __shared__ __align__(16) float  xs[30][32];       // input with zero halo
    __shared__ __align__(16) float2 mids2[4][30][32]; // cpair group, zero halo
    __shared__ __align__(16) float  w1s[288];         // [tap][32 ch]
    __shared__ __align__(16) float  w2s[288];
    __shared__ __align__(16) float  b1s[32];
    __shared__ float b2s;
    __shared__ float red1[7], red2[7], redm[7];
    __shared__ float stats[2][3];
    __shared__ float xls[2][64];

    const int tid  = threadIdx.x;
    const int lane = tid & 31, wid = tid >> 5;
    const int b    = blockIdx.x;

    // ---- feat part 1: (min1, min2, max) reduction per branch ----
    #pragma unroll
    for (int br = 0; br < 2; br++) {
        const float4* v = (const float4*)((br ? v02 : v005) + b * PIX);
        float m1 = 1e30f, m2 = 1e30f, mx = -1e30f;
        if (tid < 196) {
            const float4 q = v[tid];
            float hv;
            mx = fmaxf(fmaxf(q.x, q.y), fmaxf(q.z, q.w));
            m1 = fminf(q.x, q.y); m2 = fmaxf(q.x, q.y);
            hv = fmaxf(m1, q.z); m1 = fminf(m1, q.z); m2 = fminf(m2, hv);
            hv = fmaxf(m1, q.w); m1 = fminf(m1, q.w); m2 = fminf(m2, hv);
        }
        #pragma unroll
        for (int o = 16; o; o >>= 1) {
            const float o1 = __shfl_xor_sync(0xFFFFFFFFu, m1, o);
            const float o2 = __shfl_xor_sync(0xFFFFFFFFu, m2, o);
            const float om = __shfl_xor_sync(0xFFFFFFFFu, mx, o);
            const float hi = fmaxf(m1, o1);
            m1 = fminf(m1, o1);
            m2 = fminf(hi, fminf(m2, o2));
            mx = fmaxf(mx, om);
        }
        if (lane == 0) { red1[wid] = m1; red2[wid] = m2; redm[wid] = mx; }
        __syncthreads();
        if (tid == 0) {
            float a1 = red1[0], a2 = red2[0], am = redm[0];
            #pragma unroll
            for (int w = 1; w < 7; w++) {
                const float o1 = red1[w], o2 = red2[w];
                const float hi = fmaxf(a1, o1);
                a1 = fminf(a1, o1);
                a2 = fminf(hi, fminf(a2, o2));
                am = fmaxf(am, redm[w]);
            }
            stats[br][0] = a1; stats[br][1] = a2; stats[br][2] = am;
        }
        __syncthreads();
    }
    // 64 landscape values per branch: xls[br][k*32 + t]
    if (tid < 128) {
        const int br = tid >> 6, i = tid & 63;
        const int k = i >> 5, t = i & 31;
        const float t0 = br ? 0.05f : 0.01f;
        const float dt = br ? (0.25f / 31.0f) : (0.28f / 31.0f);
        const float tv = t0 + (float)t * dt;
        xls[br][i] = fmaxf(0.f, fminf(tv - stats[br][k], stats[br][2] - tv));
    }

    // ---- conv smem init ----
    for (int i = tid; i < 30 * 32; i += 224) (&xs[0][0])[i] = 0.f;
    for (int i = tid; i < 4 * 30 * 32; i += 224)
        (&mids2[0][0][0])[i] = make_float2(0.f, 0.f);
    for (int i = tid; i < 288; i += 224) { w1s[i] = w1[i]; w2s[i] = w2[i]; }
    if (tid < 32) b1s[tid] = b1[tid];
    if (tid == 0) b2s = b2[0];
    __syncthreads();

    // input load: 28 % 4 == 0 so float4 never crosses a row
    if (tid < 196) {
        const float4 q = ((const float4*)(x + b * PIX))[tid];
        const int r = tid / 7, c = (tid % 7) * 4;
        xs[r + 1][c + 1] = q.x; xs[r + 1][c + 2] = q.y;
        xs[r + 1][c + 3] = q.z; xs[r + 1][c + 4] = q.w;
    }
    __syncthreads();

    const bool active = tid < 196;
    const int xcol = tid % 28;
    const int y0   = (tid / 28) * 4;

    u64 xp[6][3];   // (x,x) packs, reused across all 16 channel pairs
    if (active) {
        #pragma unroll
        for (int rr = 0; rr < 6; rr++)
            #pragma unroll
            for (int dx = 0; dx < 3; dx++) {
                const float xv = xs[y0 + rr][xcol + dx];
                xp[rr][dx] = pk2(xv, xv);
            }
    }
    u64 a0 = 0, a1 = 0, a2 = 0, a3 = 0;   // packed-over-channel accumulators

    for (int g = 0; g < 4; g++) {
        if (active) {
            #pragma unroll
            for (int cp = 0; cp < 4; cp++) {
                const int c2 = (g * 4 + cp) * 2;      // even channel index
                const u64 bv = *(const u64*)&b1s[c2];
                u64 m0 = bv, m1 = bv, m2 = bv, m3 = bv;
                #pragma unroll
                for (int dy = 0; dy < 3; dy++)
                    #pragma unroll
                    for (int dx = 0; dx < 3; dx++) {
                        const u64 wv = *(const u64*)&w1s[(dy * 3 + dx) * 32 + c2];
                        m0 = fma2(xp[0 + dy][dx], wv, m0);
                        m1 = fma2(xp[1 + dy][dx], wv, m1);
                        m2 = fma2(xp[2 + dy][dx], wv, m2);
                        m3 = fma2(xp[3 + dy][dx], wv, m3);
                    }
                float lo, hi;
                upk2(m0, lo, hi);
                mids2[cp][y0 + 1][xcol + 1] = make_float2(fmaxf(lo, 0.f), fmaxf(hi, 0.f));
                upk2(m1, lo, hi);
                mids2[cp][y0 + 2][xcol + 1] = make_float2(fmaxf(lo, 0.f), fmaxf(hi, 0.f));
                upk2(m2, lo, hi);
                mids2[cp][y0 + 3][xcol + 1] = make_float2(fmaxf(lo, 0.f), fmaxf(hi, 0.f));
                upk2(m3, lo, hi);
                mids2[cp][y0 + 4][xcol + 1] = make_float2(fmaxf(lo, 0.f), fmaxf(hi, 0.f));
            }
        }
        __syncthreads();
        if (active) {
            #pragma unroll
            for (int cp = 0; cp < 4; cp++) {
                const int c2 = (g * 4 + cp) * 2;
                #pragma unroll
                for (int dx = 0; dx < 3; dx++) {
                    u64 c[6];
                    #pragma unroll
                    for (int rr = 0; rr < 6; rr++)
                        c[rr] = *(const u64*)&mids2[cp][y0 + rr][xcol + dx];
                    #pragma unroll
                    for (int dy = 0; dy < 3; dy++) {
                        const u64 wv = *(const u64*)&w2s[(dy * 3 + dx) * 32 + c2];
                        a0 = fma2(c[0 + dy], wv, a0);
                        a1 = fma2(c[1 + dy], wv, a1);
                        a2 = fma2(c[2 + dy], wv, a2);
                        a3 = fma2(c[3 + dy], wv, a3);
                    }
                }
            }
        }
        __syncthreads();
    }
    if (active) {
        const float bb = b2s;
        float lo, hi;
        float* hout = g_hconv + b * PIX + y0 * 28 + xcol;
        upk2(a0, lo, hi); hout[0]  = fmaxf(lo + hi + bb, 0.f);
        upk2(a1, lo, hi); hout[28] = fmaxf(lo + hi + bb, 0.f);
        upk2(a2, lo, hi); hout[56] = fmaxf(lo + hi + bb, 0.f);
        upk2(a3, lo, hi); hout[84] = fmaxf(lo + hi + bb, 0.f);
    }

    // ---- feat part 2: relu(xls @ g_w + g_b), warps 0-1 tail work ----
    // (xls written before the first conv __syncthreads; weights L2-resident)
    if (tid < 64) {
        const int br = tid >> 5, f = tid & 31;
        const float* gw = br ? g2w : g1w;
        float a = (br ? g2b : g1b)[f];
        #pragma unroll 8
        for (int i = 0; i < 64; i++) a += xls[br][i] * gw[i * 32 + f];
        g_feat[b * 64 + br * 32 + f] = fmaxf(a, 0.f);
    }
}

// ---------------------------------------------------------------------------
// Kernel 2: z = [hconv(784) | feat(64)]; relu(z @ fc1_w + b) @ fc2_w + b.
// 128 blocks x 256 threads; 8 samples/block; in-block split-K over 4
// warp-quarters. f32x2: each thread owns ADJACENT f-pairs so weight pairs
// arrive via one LDS.64; (z,z) packed once per sample per k.
// ---------------------------------------------------------------------------
#define FC_ZS    (8 * 852)        // padded z rows (852 breaks bank aliasing)
#define FC_WS    (4 * 53 * 64)    // 4 quarter chunks of staged fc1_w
#define FC_PH    (4 * 8 * 65)     // split-K partials
#define FC_HS    (8 * 65)
#define FC_SMEM_BYTES ((FC_ZS + FC_WS + FC_PH + FC_HS) * 4)

__global__ void __launch_bounds__(256) fc_kernel(
    const float* __restrict__ fc1w, const float* __restrict__ fc1b,
    const float* __restrict__ fc2w, const float* __restrict__ fc2b,
    float* __restrict__ out)
{
    extern __shared__ float sm[];
    float* zs = sm;                 // [8][852]
    float* ws = sm + FC_ZS;         // [4][53*64]
    float* ph = ws + FC_WS;         // [(q*8+s)][65]
    float* hs = ph + FC_PH;         // [8][65]

    const int tid = threadIdx.x;
    const int b0  = blockIdx.x * 8;

    for (int i = tid; i < 8 * 848; i += 256) {
        const int s = i / 848, k = i - s * 848;
        zs[s * 852 + k] = (k < 784) ? g_hconv[(b0 + s) * 784 + k]
                                    : g_feat[(b0 + s) * 64 + (k - 784)];
    }

    const int q  = tid >> 6;          // k-quarter (0..3), 212 k's each
    const int sq = (tid >> 4) & 3;    // samples sq, sq+4
    const int fq = tid & 15;          // f = 2*fq, 2*fq+1, 2*fq+32, 2*fq+33
    const int lt = tid & 63;

    u64 acc[2][2] = {{0, 0}, {0, 0}};  // [sample][f-pair chunk]
    const float* z0p = zs + sq * 852;
    const float* z1p = zs + (sq + 4) * 852;
    float* wq = ws + q * (53 * 64);

    for (int c = 0; c < 4; c++) {
        __syncthreads();              // zs ready (c=0); wq consumed (c>0)
        const float* wsrc = fc1w + (q * 212 + c * 53) * 64;
        for (int i = lt; i < 53 * 64; i += 64) wq[i] = wsrc[i];
        __syncthreads();
        const int kb = q * 212 + c * 53;
        for (int kk = 0; kk < 53; kk++) {
            const float z0 = z0p[kb + kk];
            const float z1 = z1p[kb + kk];
            const u64 zz0 = pk2(z0, z0);
            const u64 zz1 = pk2(z1, z1);
            const float* wrow = wq + kk * 64 + fq * 2;
            const u64 w0 = *(const u64*)(wrow);
            const u64 w1 = *(const u64*)(wrow + 32);
            acc[0][0] = fma2(zz0, w0, acc[0][0]);
            acc[0][1] = fma2(zz0, w1, acc[0][1]);
            acc[1][0] = fma2(zz1, w0, acc[1][0]);
            acc[1][1] = fma2(zz1, w1, acc[1][1]);
        }
    }
    {
        float lo, hi;
        float* p0 = ph + (q * 8 + sq) * 65;
        float* p1 = ph + (q * 8 + sq + 4) * 65;
        upk2(acc[0][0], lo, hi); p0[fq * 2]      = lo; p0[fq * 2 + 1]  = hi;
        upk2(acc[0][1], lo, hi); p0[fq * 2 + 32] = lo; p0[fq * 2 + 33] = hi;
        upk2(acc[1][0], lo, hi); p1[fq * 2]      = lo; p1[fq * 2 + 1]  = hi;
        upk2(acc[1][1], lo, hi); p1[fq * 2 + 32] = lo; p1[fq * 2 + 33] = hi;
    }
    __syncthreads();
    for (int i = tid; i < 512; i += 256) {
        const int s = i >> 6, f = i & 63;
        float h = ph[s * 65 + f] + ph[(8 + s) * 65 + f]
                + ph[(16 + s) * 65 + f] + ph[(24 + s) * 65 + f] + fc1b[f];
        hs[s * 65 + f] = fmaxf(h, 0.f);
    }
    __syncthreads();
    if (tid < 80) {
        const int s = tid / 10, o = tid - s * 10;
        float a = fc2b[o];
        #pragma unroll
        for (int f = 0; f < 64; f++) a += hs[s * 65 + f] * fc2w[f * 10 + o];
        out[(b0 + s) * 10 + o] = a;
    }
}

// ---------------------------------------------------------------------------
extern "C" void kernel_launch(void* const* d_in, const int* in_sizes, int n_in,
                              void* d_out, int out_size)
{
    const float* x       = (const float*)d_in[0];
    const float* xd005   = (const float*)d_in[1];
    const float* xd02    = (const float*)d_in[2];
    const float* conv_w1 = (const float*)d_in[3];
    const float* conv_b1 = (const float*)d_in[4];
    const float* conv_w2 = (const float*)d_in[5];
    const float* conv_b2 = (const float*)d_in[6];
    const float* g1w     = (const float*)d_in[7];
    const float* g1b     = (const float*)d_in[8];
    const float* g2w     = (const float*)d_in[9];
    const float* g2b     = (const float*)d_in[10];
    const float* fc1w    = (const float*)d_in[11];
    const float* fc1b    = (const float*)d_in[12];
    const float* fc2w    = (const float*)d_in[13];
    const float* fc2b    = (const float*)d_in[14];
    float* out = (float*)d_out;

    cudaFuncSetAttribute(fc_kernel, cudaFuncAttributeMaxDynamicSharedMemorySize,
                         FC_SMEM_BYTES);

    conv_feat_kernel<<<BATCH, 224>>>(x, conv_w1, conv_b1, conv_w2, conv_b2,
                                     xd005, xd02, g1w, g1b, g2w, g2b);
    fc_kernel<<<128, 256, FC_SMEM_BYTES>>>(fc1w, fc1b, fc2w, fc2b, out);
}

// round 9
// speedup vs baseline: 1.3496x; 1.0683x over previous
#include <cuda_runtime.h>

#define BATCH 1024
#define PIX   784

// Scratch (allocation-free rule: __device__ globals)
__device__ float g_feat[BATCH * 64];    // [B][branch0 32 | branch1 32]
__device__ float g_hconv[BATCH * PIX];  // CNN branch output, flattened

// ---- packed f32x2 helpers (Blackwell FFMA2: only reachable via PTX) --------
typedef unsigned long long u64;
__device__ __forceinline__ u64 pk2(float lo, float hi) {
    u64 r; asm("mov.b64 %0, {%1,%2};" : "=l"(r) : "f"(lo), "f"(hi)); return r;
}
__device__ __forceinline__ void upk2(u64 v, float& lo, float& hi) {
    asm("mov.b64 {%0,%1}, %2;" : "=f"(lo), "=f"(hi) : "l"(v));
}
__device__ __forceinline__ u64 fma2(u64 a, u64 b, u64 c) {
    u64 d; asm("fma.rn.f32x2 %0, %1, %2, %3;" : "=l"(d) : "l"(a), "l"(b), "l"(c));
    return d;
}

// ---------------------------------------------------------------------------
// Kernel 1 (fused): per-sample block does BOTH:
//  (a) persistence-landscape features. tent(v)=max(0,min(t-v,death-t)) is
//      non-increasing in v, so top-2 over p at every t = tents of the two
//      SMALLEST v -> only (min1,min2,max) per sample + 64 closed-form evals
//      + 64x64 matvec. DRAM latency hides behind conv FMA work.
//  (b) fused conv(1->32,3x3,SAME)->relu->conv(32->1,3x3,SAME)->relu with
//      CHANNEL-PAIR f32x2 packing (weight pairs adjacent -> free LDS.64;
//      mids stored as float2 -> free LDS.64). FFMA2 = 2x fma throughput.
// 224 threads; 196 active for conv: 28 cols x 7 groups of 4 rows.
// ---------------------------------------------------------------------------
__global__ void __launch_bounds__(224) conv_feat_kernel(
    const float* __restrict__ x,
    const float* __restrict__ w1, const float* __restrict__ b1,
    const float* __restrict__ w2, const float* __restrict__ b2,
    const float* __restrict__ v005, const float* __restrict__ v02,
    const float* __restrict__ g1w, const float* __restrict__ g1b,
    const float* __restrict__ g2w, const float* __restrict__ g2b)
{
    __shared__ __align__(16) float  xs[30][32];       // input with zero halo
    __shared__ __align__(16) float2 mids2[4][30][32]; // cpair group, zero halo
    __shared__ __align__(16) float  w1s[288];         // [tap][32 ch]
    __shared__ __align__(16) float  w2s[288];
    __shared__ __align__(16) float  b1s[32];
    __shared__ float b2s;
    __shared__ float red1[7], red2[7], redm[7];
    __shared__ float stats[2][3];
    __shared__ float xls[2][64];

    const int tid  = threadIdx.x;
    const int lane = tid & 31, wid = tid >> 5;
    const int b    = blockIdx.x;

    // ---- feat part 1: (min1, min2, max) reduction per branch ----
    #pragma unroll
    for (int br = 0; br < 2; br++) {
        const float4* v = (const float4*)((br ? v02 : v005) + b * PIX);
        float m1 = 1e30f, m2 = 1e30f, mx = -1e30f;
        if (tid < 196) {
            const float4 q = v[tid];
            float hv;
            mx = fmaxf(fmaxf(q.x, q.y), fmaxf(q.z, q.w));
            m1 = fminf(q.x, q.y); m2 = fmaxf(q.x, q.y);
            hv = fmaxf(m1, q.z); m1 = fminf(m1, q.z); m2 = fminf(m2, hv);
            hv = fmaxf(m1, q.w); m1 = fminf(m1, q.w); m2 = fminf(m2, hv);
        }
        #pragma unroll
        for (int o = 16; o; o >>= 1) {
            const float o1 = __shfl_xor_sync(0xFFFFFFFFu, m1, o);
            const float o2 = __shfl_xor_sync(0xFFFFFFFFu, m2, o);
            const float om = __shfl_xor_sync(0xFFFFFFFFu, mx, o);
            const float hi = fmaxf(m1, o1);
            m1 = fminf(m1, o1);
            m2 = fminf(hi, fminf(m2, o2));
            mx = fmaxf(mx, om);
        }
        if (lane == 0) { red1[wid] = m1; red2[wid] = m2; redm[wid] = mx; }
        __syncthreads();
        if (tid == 0) {
            float a1 = red1[0], a2 = red2[0], am = redm[0];
            #pragma unroll
            for (int w = 1; w < 7; w++) {
                const float o1 = red1[w], o2 = red2[w];
                const float hi = fmaxf(a1, o1);
                a1 = fminf(a1, o1);
                a2 = fminf(hi, fminf(a2, o2));
                am = fmaxf(am, redm[w]);
            }
            stats[br][0] = a1; stats[br][1] = a2; stats[br][2] = am;
        }
        __syncthreads();
    }
    // 64 landscape values per branch: xls[br][k*32 + t]
    if (tid < 128) {
        const int br = tid >> 6, i = tid & 63;
        const int k = i >> 5, t = i & 31;
        const float t0 = br ? 0.05f : 0.01f;
        const float dt = br ? (0.25f / 31.0f) : (0.28f / 31.0f);
        const float tv = t0 + (float)t * dt;
        xls[br][i] = fmaxf(0.f, fminf(tv - stats[br][k], stats[br][2] - tv));
    }

    // ---- conv smem init ----
    for (int i = tid; i < 30 * 32; i += 224) (&xs[0][0])[i] = 0.f;
    for (int i = tid; i < 4 * 30 * 32; i += 224)
        (&mids2[0][0][0])[i] = make_float2(0.f, 0.f);
    for (int i = tid; i < 288; i += 224) { w1s[i] = w1[i]; w2s[i] = w2[i]; }
    if (tid < 32) b1s[tid] = b1[tid];
    if (tid == 0) b2s = b2[0];
    __syncthreads();

    // input load: 28 % 4 == 0 so float4 never crosses a row
    if (tid < 196) {
        const float4 q = ((const float4*)(x + b * PIX))[tid];
        const int r = tid / 7, c = (tid % 7) * 4;
        xs[r + 1][c + 1] = q.x; xs[r + 1][c + 2] = q.y;
        xs[r + 1][c + 3] = q.z; xs[r + 1][c + 4] = q.w;
    }
    __syncthreads();

    const bool active = tid < 196;
    const int xcol = tid % 28;
    const int y0   = (tid / 28) * 4;

    u64 xp[6][3];   // (x,x) packs, reused across all 16 channel pairs
    if (active) {
        #pragma unroll
        for (int rr = 0; rr < 6; rr++)
            #pragma unroll
            for (int dx = 0; dx < 3; dx++) {
                const float xv = xs[y0 + rr][xcol + dx];
                xp[rr][dx] = pk2(xv, xv);
            }
    }
    u64 a0 = 0, a1 = 0, a2 = 0, a3 = 0;   // packed-over-channel accumulators

    for (int g = 0; g < 4; g++) {
        if (active) {
            #pragma unroll
            for (int cp = 0; cp < 4; cp++) {
                const int c2 = (g * 4 + cp) * 2;      // even channel index
                const u64 bv = *(const u64*)&b1s[c2];
                u64 m0 = bv, m1 = bv, m2 = bv, m3 = bv;
                #pragma unroll
                for (int dy = 0; dy < 3; dy++)
                    #pragma unroll
                    for (int dx = 0; dx < 3; dx++) {
                        const u64 wv = *(const u64*)&w1s[(dy * 3 + dx) * 32 + c2];
                        m0 = fma2(xp[0 + dy][dx], wv, m0);
                        m1 = fma2(xp[1 + dy][dx], wv, m1);
                        m2 = fma2(xp[2 + dy][dx], wv, m2);
                        m3 = fma2(xp[3 + dy][dx], wv, m3);
                    }
                float lo, hi;
                upk2(m0, lo, hi);
                mids2[cp][y0 + 1][xcol + 1] = make_float2(fmaxf(lo, 0.f), fmaxf(hi, 0.f));
                upk2(m1, lo, hi);
                mids2[cp][y0 + 2][xcol + 1] = make_float2(fmaxf(lo, 0.f), fmaxf(hi, 0.f));
                upk2(m2, lo, hi);
                mids2[cp][y0 + 3][xcol + 1] = make_float2(fmaxf(lo, 0.f), fmaxf(hi, 0.f));
                upk2(m3, lo, hi);
                mids2[cp][y0 + 4][xcol + 1] = make_float2(fmaxf(lo, 0.f), fmaxf(hi, 0.f));
            }
        }
        __syncthreads();
        if (active) {
            #pragma unroll
            for (int cp = 0; cp < 4; cp++) {
                const int c2 = (g * 4 + cp) * 2;
                #pragma unroll
                for (int dx = 0; dx < 3; dx++) {
                    u64 c[6];
                    #pragma unroll
                    for (int rr = 0; rr < 6; rr++)
                        c[rr] = *(const u64*)&mids2[cp][y0 + rr][xcol + dx];
                    #pragma unroll
                    for (int dy = 0; dy < 3; dy++) {
                        const u64 wv = *(const u64*)&w2s[(dy * 3 + dx) * 32 + c2];
                        a0 = fma2(c[0 + dy], wv, a0);
                        a1 = fma2(c[1 + dy], wv, a1);
                        a2 = fma2(c[2 + dy], wv, a2);
                        a3 = fma2(c[3 + dy], wv, a3);
                    }
                }
            }
        }
        __syncthreads();
    }
    if (active) {
        const float bb = b2s;
        float lo, hi;
        float* hout = g_hconv + b * PIX + y0 * 28 + xcol;
        upk2(a0, lo, hi); hout[0]  = fmaxf(lo + hi + bb, 0.f);
        upk2(a1, lo, hi); hout[28] = fmaxf(lo + hi + bb, 0.f);
        upk2(a2, lo, hi); hout[56] = fmaxf(lo + hi + bb, 0.f);
        upk2(a3, lo, hi); hout[84] = fmaxf(lo + hi + bb, 0.f);
    }

    // ---- feat part 2: relu(xls @ g_w + g_b), warps 0-1 tail work ----
    if (tid < 64) {
        const int br = tid >> 5, f = tid & 31;
        const float* gw = br ? g2w : g1w;
        float a = (br ? g2b : g1b)[f];
        #pragma unroll 8
        for (int i = 0; i < 64; i++) a += xls[br][i] * gw[i * 32 + f];
        g_feat[b * 64 + br * 32 + f] = fmaxf(a, 0.f);
    }
}

// ---------------------------------------------------------------------------
// Kernel 2: z = [hconv(784) | feat(64)]; relu(z @ fc1_w + b) @ fc2_w + b.
// 256 blocks x 256 threads; 4 samples/block (occupancy fix: 2-3 CTAs/SM vs
// 1 before). In-block split-K over 4 warp-quarters; each thread owns ONE
// sample x two adjacent-f f32x2 pairs; fully cooperative float4 weight
// staging. FFMA2 via fma.rn.f32x2.
// ---------------------------------------------------------------------------
#define FC_S     4                 // samples per block
#define FC_CH    53                // staged k-rows per quarter-chunk
#define FC_ZS    (FC_S * 852)      // padded z rows
#define FC_WS    (4 * FC_CH * 64)  // 4 quarter chunks of staged fc1_w
#define FC_PH    (4 * FC_S * 65)   // split-K partials
#define FC_HS    (FC_S * 65)
#define FC_SMEM_BYTES ((FC_ZS + FC_WS + FC_PH + FC_HS) * 4)

__global__ void __launch_bounds__(256) fc_kernel(
    const float* __restrict__ fc1w, const float* __restrict__ fc1b,
    const float* __restrict__ fc2w, const float* __restrict__ fc2b,
    float* __restrict__ out)
{
    extern __shared__ float sm[];
    float* zs = sm;                 // [4][852]
    float* ws = sm + FC_ZS;         // [4][53*64]
    float* ph = ws + FC_WS;         // [(q*4+s)][65]
    float* hs = ph + FC_PH;         // [4][65]

    const int tid = threadIdx.x;
    const int b0  = blockIdx.x * FC_S;

    for (int i = tid; i < FC_S * 212; i += 256) {   // float4-granular z load
        const int s = i / 212, k4 = i - s * 212;
        float4 q;
        if (k4 < 196)      q = ((const float4*)(g_hconv + (b0 + s) * 784))[k4];
        else               q = ((const float4*)(g_feat  + (b0 + s) * 64))[k4 - 196];
        float* zp = zs + s * 852 + k4 * 4;
        zp[0] = q.x; zp[1] = q.y; zp[2] = q.z; zp[3] = q.w;
    }

    const int q  = tid >> 6;          // k-quarter (0..3), 212 k's each
    const int sq = (tid >> 4) & 3;    // sample (0..3)
    const int fq = tid & 15;          // f = 2*fq, 2*fq+1, 2*fq+32, 2*fq+33

    u64 acc0 = 0, acc1 = 0;
    const float* zp = zs + sq * 852;

    for (int c = 0; c < 4; c++) {
        __syncthreads();              // zs ready (c=0); ws consumed (c>0)
        // cooperative staging of ALL four quarter chunks (float4)
        for (int i = tid; i < 4 * FC_CH * 16; i += 256) {
            const int ch = i / (FC_CH * 16);          // which quarter
            const int j  = i - ch * (FC_CH * 16);     // f4 index in chunk
            ((float4*)ws)[i] =
                ((const float4*)fc1w)[(ch * 212 + c * FC_CH) * 16 + j];
        }
        __syncthreads();
        const int kb = q * 212 + c * FC_CH;
        const float* wq = ws + q * (FC_CH * 64) + fq * 2;
        #pragma unroll 4
        for (int kk = 0; kk < FC_CH; kk++) {
            const float z = zp[kb + kk];
            const u64 zz = pk2(z, z);
            const float* wrow = wq + kk * 64;
            acc0 = fma2(zz, *(const u64*)(wrow),      acc0);
            acc1 = fma2(zz, *(const u64*)(wrow + 32), acc1);
        }
    }
    {
        float lo, hi;
        float* p = ph + (q * FC_S + sq) * 65;
        upk2(acc0, lo, hi); p[fq * 2]      = lo; p[fq * 2 + 1]  = hi;
        upk2(acc1, lo, hi); p[fq * 2 + 32] = lo; p[fq * 2 + 33] = hi;
    }
    __syncthreads();
    if (tid < FC_S * 64) {
        const int s = tid >> 6, f = tid & 63;
        float h = ph[s * 65 + f] + ph[(FC_S + s) * 65 + f]
                + ph[(2 * FC_S + s) * 65 + f] + ph[(3 * FC_S + s) * 65 + f]
                + fc1b[f];
        hs[s * 65 + f] = fmaxf(h, 0.f);
    }
    __syncthreads();
    if (tid < FC_S * 10) {
        const int s = tid / 10, o = tid - s * 10;
        float a = fc2b[o];
        #pragma unroll
        for (int f = 0; f < 64; f++) a += hs[s * 65 + f] * fc2w[f * 10 + o];
        out[(b0 + s) * 10 + o] = a;
    }
}

// ---------------------------------------------------------------------------
extern "C" void kernel_launch(void* const* d_in, const int* in_sizes, int n_in,
                              void* d_out, int out_size)
{
    const float* x       = (const float*)d_in[0];
    const float* xd005   = (const float*)d_in[1];
    const float* xd02    = (const float*)d_in[2];
    const float* conv_w1 = (const float*)d_in[3];
    const float* conv_b1 = (const float*)d_in[4];
    const float* conv_w2 = (const float*)d_in[5];
    const float* conv_b2 = (const float*)d_in[6];
    const float* g1w     = (const float*)d_in[7];
    const float* g1b     = (const float*)d_in[8];
    const float* g2w     = (const float*)d_in[9];
    const float* g2b     = (const float*)d_in[10];
    const float* fc1w    = (const float*)d_in[11];
    const float* fc1b    = (const float*)d_in[12];
    const float* fc2w    = (const float*)d_in[13];
    const float* fc2b    = (const float*)d_in[14];
    float* out = (float*)d_out;

    cudaFuncSetAttribute(fc_kernel, cudaFuncAttributeMaxDynamicSharedMemorySize,
                         FC_SMEM_BYTES);

    conv_feat_kernel<<<BATCH, 224>>>(x, conv_w1, conv_b1, conv_w2, conv_b2,
                                     xd005, xd02, g1w, g1b, g2w, g2b);
    fc_kernel<<<256, 256, FC_SMEM_BYTES>>>(fc1w, fc1b, fc2w, fc2b, out);
}